// round 4
// baseline (speedup 1.0000x reference)
#include <cuda_runtime.h>

// Shapes fixed by the problem
#define BB 16
#define XL 1024
#define YL 1024
#define DD 1024

#define NEG_INF (-1e20f)

// Tiling
#define BM 128
#define BN 128
#define BK 16

// ---------------------------------------------------------------------------
// Kernel 1: scores[b,x,y] = sum_d xs[b,x,d] * ys[b,y,d]   (NT GEMM)
// masked store: mask_ys[b,y]==0 -> NEG_INF
// ---------------------------------------------------------------------------
__global__ __launch_bounds__(256, 2)
void scores_kernel(const float* __restrict__ xs,
                   const float* __restrict__ ys,
                   const int* __restrict__ mask,
                   float* __restrict__ w)
{
    __shared__ float As[BK][BM + 4];
    __shared__ float Bs[BK][BN + 4];

    const int b = blockIdx.z;
    const int rowBase = blockIdx.y * BM;   // x
    const int colBase = blockIdx.x * BN;   // y

    const float* A  = xs + (size_t)b * XL * DD + (size_t)rowBase * DD;
    const float* Bp = ys + (size_t)b * YL * DD + (size_t)colBase * DD;

    const int t  = threadIdx.x;      // 0..255
    const int tx = t & 15;
    const int ty = t >> 4;

    float acc[8][8];
#pragma unroll
    for (int i = 0; i < 8; ++i)
#pragma unroll
        for (int j = 0; j < 8; ++j) acc[i][j] = 0.0f;

    for (int k0 = 0; k0 < DD; k0 += BK) {
        // Load 128x16 tiles of A and B (K-contiguous), scatter transposed.
#pragma unroll
        for (int i = 0; i < 2; ++i) {
            int f  = t + i * 256;    // 0..511 float4 slots
            int r  = f >> 2;         // 0..127 row
            int c4 = f & 3;          // float4 within the 16-wide K slice
            float4 va = *reinterpret_cast<const float4*>(A  + (size_t)r * DD + k0 + c4 * 4);
            float4 vb = *reinterpret_cast<const float4*>(Bp + (size_t)r * DD + k0 + c4 * 4);
            As[c4 * 4 + 0][r] = va.x; As[c4 * 4 + 1][r] = va.y;
            As[c4 * 4 + 2][r] = va.z; As[c4 * 4 + 3][r] = va.w;
            Bs[c4 * 4 + 0][r] = vb.x; Bs[c4 * 4 + 1][r] = vb.y;
            Bs[c4 * 4 + 2][r] = vb.z; Bs[c4 * 4 + 3][r] = vb.w;
        }
        __syncthreads();

#pragma unroll
        for (int k = 0; k < BK; ++k) {
            float4 a0 = *reinterpret_cast<const float4*>(&As[k][ty * 8]);
            float4 a1 = *reinterpret_cast<const float4*>(&As[k][ty * 8 + 4]);
            float4 b0 = *reinterpret_cast<const float4*>(&Bs[k][tx * 8]);
            float4 b1 = *reinterpret_cast<const float4*>(&Bs[k][tx * 8 + 4]);
            float af[8] = {a0.x, a0.y, a0.z, a0.w, a1.x, a1.y, a1.z, a1.w};
            float bf[8] = {b0.x, b0.y, b0.z, b0.w, b1.x, b1.y, b1.z, b1.w};
#pragma unroll
            for (int i = 0; i < 8; ++i)
#pragma unroll
                for (int j = 0; j < 8; ++j)
                    acc[i][j] = fmaf(af[i], bf[j], acc[i][j]);
        }
        __syncthreads();
    }

    // Masked epilogue store
    int msk[8];
#pragma unroll
    for (int j = 0; j < 8; ++j)
        msk[j] = mask[b * YL + colBase + tx * 8 + j];

    float* wrow = w + (size_t)b * XL * YL + (size_t)(rowBase + ty * 8) * YL + colBase + tx * 8;
#pragma unroll
    for (int i = 0; i < 8; ++i) {
        float4 o0, o1;
        o0.x = msk[0] ? acc[i][0] : NEG_INF;
        o0.y = msk[1] ? acc[i][1] : NEG_INF;
        o0.z = msk[2] ? acc[i][2] : NEG_INF;
        o0.w = msk[3] ? acc[i][3] : NEG_INF;
        o1.x = msk[4] ? acc[i][4] : NEG_INF;
        o1.y = msk[5] ? acc[i][5] : NEG_INF;
        o1.z = msk[6] ? acc[i][6] : NEG_INF;
        o1.w = msk[7] ? acc[i][7] : NEG_INF;
        *reinterpret_cast<float4*>(wrow + (size_t)i * YL)     = o0;
        *reinterpret_cast<float4*>(wrow + (size_t)i * YL + 4) = o1;
    }
}

// ---------------------------------------------------------------------------
// Kernel 2: in-place row softmax over YL=1024, one block (256 thr) per row
// ---------------------------------------------------------------------------
__global__ __launch_bounds__(256)
void softmax_kernel(float* __restrict__ w)
{
    __shared__ float red[256];
    const int row = blockIdx.x;                 // 0 .. B*XL-1
    float* p = w + (size_t)row * YL;
    const int t = threadIdx.x;

    float4 v = reinterpret_cast<float4*>(p)[t]; // 4 contiguous per thread

    float m = fmaxf(fmaxf(v.x, v.y), fmaxf(v.z, v.w));
    red[t] = m;
    __syncthreads();
    for (int s = 128; s > 0; s >>= 1) {
        if (t < s) red[t] = fmaxf(red[t], red[t + s]);
        __syncthreads();
    }
    m = red[0];
    __syncthreads();

    float e0 = expf(v.x - m);
    float e1 = expf(v.y - m);
    float e2 = expf(v.z - m);
    float e3 = expf(v.w - m);

    red[t] = e0 + e1 + e2 + e3;
    __syncthreads();
    for (int s = 128; s > 0; s >>= 1) {
        if (t < s) red[t] += red[t + s];
        __syncthreads();
    }
    float inv = 1.0f / red[0];

    float4 o;
    o.x = e0 * inv; o.y = e1 * inv; o.z = e2 * inv; o.w = e3 * inv;
    reinterpret_cast<float4*>(p)[t] = o;
}

// ---------------------------------------------------------------------------
// Kernel 3: emb[b,x,d] = sum_y w[b,x,y] * ys[b,y,d]   (NN GEMM)
// ---------------------------------------------------------------------------
__global__ __launch_bounds__(256, 2)
void emb_kernel(const float* __restrict__ w,
                const float* __restrict__ ys,
                float* __restrict__ emb)
{
    __shared__ float As[BK][BM + 4];
    __shared__ float Bs[BK][BN + 4];

    const int b = blockIdx.z;
    const int rowBase = blockIdx.y * BM;   // x
    const int colBase = blockIdx.x * BN;   // d

    const float* A  = w  + (size_t)b * XL * YL + (size_t)rowBase * YL;
    const float* Bp = ys + (size_t)b * YL * DD;

    const int t  = threadIdx.x;
    const int tx = t & 15;
    const int ty = t >> 4;

    float acc[8][8];
#pragma unroll
    for (int i = 0; i < 8; ++i)
#pragma unroll
        for (int j = 0; j < 8; ++j) acc[i][j] = 0.0f;

    for (int k0 = 0; k0 < YL; k0 += BK) {
        // A tile: 128 rows x 16 K (K contiguous) -> transpose scatter
#pragma unroll
        for (int i = 0; i < 2; ++i) {
            int f  = t + i * 256;
            int r  = f >> 2;
            int c4 = f & 3;
            float4 va = *reinterpret_cast<const float4*>(A + (size_t)r * YL + k0 + c4 * 4);
            As[c4 * 4 + 0][r] = va.x; As[c4 * 4 + 1][r] = va.y;
            As[c4 * 4 + 2][r] = va.z; As[c4 * 4 + 3][r] = va.w;
        }
        // B tile: 16 K-rows x 128 N (N contiguous) -> direct copy
#pragma unroll
        for (int i = 0; i < 2; ++i) {
            int f  = t + i * 256;     // 0..511 float4 slots
            int r  = f >> 5;          // 0..15 K-row
            int c4 = f & 31;          // float4 within 128-wide N
            float4 vb = *reinterpret_cast<const float4*>(
                Bp + (size_t)(k0 + r) * DD + colBase + c4 * 4);
            *reinterpret_cast<float4*>(&Bs[r][c4 * 4]) = vb;
        }
        __syncthreads();

#pragma unroll
        for (int k = 0; k < BK; ++k) {
            float4 a0 = *reinterpret_cast<const float4*>(&As[k][ty * 8]);
            float4 a1 = *reinterpret_cast<const float4*>(&As[k][ty * 8 + 4]);
            float4 b0 = *reinterpret_cast<const float4*>(&Bs[k][tx * 8]);
            float4 b1 = *reinterpret_cast<const float4*>(&Bs[k][tx * 8 + 4]);
            float af[8] = {a0.x, a0.y, a0.z, a0.w, a1.x, a1.y, a1.z, a1.w};
            float bf[8] = {b0.x, b0.y, b0.z, b0.w, b1.x, b1.y, b1.z, b1.w};
#pragma unroll
            for (int i = 0; i < 8; ++i)
#pragma unroll
                for (int j = 0; j < 8; ++j)
                    acc[i][j] = fmaf(af[i], bf[j], acc[i][j]);
        }
        __syncthreads();
    }

    float* crow = emb + (size_t)b * XL * DD + (size_t)(rowBase + ty * 8) * DD + colBase + tx * 8;
#pragma unroll
    for (int i = 0; i < 8; ++i) {
        float4 o0, o1;
        o0.x = acc[i][0]; o0.y = acc[i][1]; o0.z = acc[i][2]; o0.w = acc[i][3];
        o1.x = acc[i][4]; o1.y = acc[i][5]; o1.z = acc[i][6]; o1.w = acc[i][7];
        *reinterpret_cast<float4*>(crow + (size_t)i * DD)     = o0;
        *reinterpret_cast<float4*>(crow + (size_t)i * DD + 4) = o1;
    }
}

// ---------------------------------------------------------------------------
extern "C" void kernel_launch(void* const* d_in, const int* in_sizes, int n_in,
                              void* d_out, int out_size)
{
    const float* xs   = (const float*)d_in[0];
    const float* ys   = (const float*)d_in[1];
    const int*   mask = (const int*)d_in[2];

    float* emb = (float*)d_out;                                  // [B, XL, D]
    float* w   = (float*)d_out + (size_t)BB * XL * DD;           // [B, XL, YL]

    dim3 block(256);
    dim3 gridS(YL / BN, XL / BM, BB);
    scores_kernel<<<gridS, block>>>(xs, ys, mask, w);

    softmax_kernel<<<BB * XL, block>>>(w);

    dim3 gridE(DD / BN, XL / BM, BB);
    emb_kernel<<<gridE, block>>>(w, ys, emb);
}

// round 6
// speedup vs baseline: 1.5409x; 1.5409x over previous
#include <cuda_runtime.h>

// Shapes fixed by the problem
#define BB 16
#define XL 1024
#define YL 1024
#define DD 1024
#define NEG_INF (-1e20f)

// ---------------------------------------------------------------------------
// SMEM layout (dynamic): four 16KB operand tiles (128 rows x 128B, SW128
// swizzled, K-major) + 512B mask region.
// ---------------------------------------------------------------------------
#define OFF_A_HI 0
#define OFF_A_LO 16384
#define OFF_B_HI 32768
#define OFF_B_LO 49152
#define OFF_MASK 65536
#define SMEM_BYTES (65536 + 512)

// ---------------------------------------------------------------------------
// Helpers
// ---------------------------------------------------------------------------
static __device__ __forceinline__ unsigned smem_u32(const void* p) {
    unsigned a;
    asm("{ .reg .u64 t; cvta.to.shared.u64 t, %1; cvt.u32.u64 %0, t; }"
        : "=r"(a) : "l"(p));
    return a;
}
static __device__ __forceinline__ float tf32_rna(float x) {
    unsigned u;
    asm("cvt.rna.tf32.f32 %0, %1;" : "=r"(u) : "f"(x));
    return __uint_as_float(u);
}
static __device__ __forceinline__ void split4(float4 v, float4& h, float4& l) {
    h.x = tf32_rna(v.x); l.x = tf32_rna(v.x - h.x);
    h.y = tf32_rna(v.y); l.y = tf32_rna(v.y - h.y);
    h.z = tf32_rna(v.z); l.z = tf32_rna(v.z - h.z);
    h.w = tf32_rna(v.w); l.w = tf32_rna(v.w - h.w);
}

#define LDSM_X4(r, addr)                                                      \
    asm volatile(                                                             \
        "ldmatrix.sync.aligned.m8n8.x4.shared.b16 {%0,%1,%2,%3}, [%4];"       \
        : "=r"((r)[0]), "=r"((r)[1]), "=r"((r)[2]), "=r"((r)[3])              \
        : "r"(addr))

#define MMA_TF32(d, a, b0, b1)                                                \
    asm volatile(                                                             \
        "mma.sync.aligned.m16n8k8.row.col.f32.tf32.tf32.f32 "                 \
        "{%0,%1,%2,%3}, {%4,%5,%6,%7}, {%8,%9}, {%0,%1,%2,%3};"               \
        : "+f"((d)[0]), "+f"((d)[1]), "+f"((d)[2]), "+f"((d)[3])              \
        : "r"((a)[0]), "r"((a)[1]), "r"((a)[2]), "r"((a)[3]),                 \
          "r"(b0), "r"(b1))

// ---------------------------------------------------------------------------
// Shared MMA mainloop over one K-chunk already resident in smem.
// 4 warps, warp tile 64x64: 4 m16 tiles x 8 n8 tiles; 3xTF32 products.
// ---------------------------------------------------------------------------
static __device__ __forceinline__ void mma_chunk(
    unsigned sb, unsigned aRow, unsigned bRow, unsigned cA, unsigned cB,
    unsigned xr, float acc[4][8][4])
{
    unsigned fa[4][4], fb[4][4], fc[4][4];
#pragma unroll
    for (int k8 = 0; k8 < 4; ++k8) {
        const unsigned colA = ((unsigned)(k8 * 32) + cA) ^ xr;
        const unsigned colB = ((unsigned)(k8 * 32) + cB) ^ xr;
#pragma unroll
        for (int i = 0; i < 4; ++i)
            LDSM_X4(fa[i], sb + OFF_A_HI + aRow + 2048u * i + colA);
#pragma unroll
        for (int jp = 0; jp < 4; ++jp)
            LDSM_X4(fb[jp], sb + OFF_B_HI + bRow + 2048u * jp + colB);
#pragma unroll
        for (int i = 0; i < 4; ++i)
            LDSM_X4(fc[i], sb + OFF_A_LO + aRow + 2048u * i + colA);

        // hi * hi
#pragma unroll
        for (int i = 0; i < 4; ++i)
#pragma unroll
            for (int j = 0; j < 8; ++j)
                MMA_TF32(acc[i][j], fa[i], fb[j >> 1][(j & 1) * 2],
                         fb[j >> 1][(j & 1) * 2 + 1]);
        // lo * hi
#pragma unroll
        for (int i = 0; i < 4; ++i)
#pragma unroll
            for (int j = 0; j < 8; ++j)
                MMA_TF32(acc[i][j], fc[i], fb[j >> 1][(j & 1) * 2],
                         fb[j >> 1][(j & 1) * 2 + 1]);
        // hi * lo
#pragma unroll
        for (int jp = 0; jp < 4; ++jp)
            LDSM_X4(fc[jp], sb + OFF_B_LO + bRow + 2048u * jp + colB);
#pragma unroll
        for (int i = 0; i < 4; ++i)
#pragma unroll
            for (int j = 0; j < 8; ++j)
                MMA_TF32(acc[i][j], fa[i], fc[j >> 1][(j & 1) * 2],
                         fc[j >> 1][(j & 1) * 2 + 1]);
    }
}

// ---------------------------------------------------------------------------
// Kernel 1: scores = xs @ ys^T with mask fused (HMMA tf32 3x)
// ---------------------------------------------------------------------------
__global__ __launch_bounds__(128, 2)
void scores_tc_kernel(const float* __restrict__ xs,
                      const float* __restrict__ ys,
                      const int* __restrict__ mask,
                      float* __restrict__ w)
{
    extern __shared__ char smem[];
    const unsigned sb = smem_u32(smem);
    const int t = threadIdx.x;
    const int wid = t >> 5;
    const int lane = t & 31;
    const int b = blockIdx.z;
    const int rowBase = blockIdx.y * 128;
    const int colBase = blockIdx.x * 128;

    const int m0 = (wid & 1) * 64;
    const int n0 = (wid >> 1) * 64;

    // fragment address geometry
    const unsigned xr = (unsigned)(lane & 7) << 4;
    const unsigned rA = (unsigned)((lane & 7) + ((lane >> 3) & 1) * 8);
    const unsigned cA = (unsigned)((lane >> 4) << 4);
    const unsigned rB = (unsigned)((lane & 7) + ((lane >> 4) & 1) * 8);
    const unsigned cB = (unsigned)(((lane >> 3) & 1) << 4);
    const unsigned aRow = ((unsigned)m0 + rA) * 128u;
    const unsigned bRow = ((unsigned)n0 + rB) * 128u;

    if (t < 128)
        ((int*)(smem + OFF_MASK))[t] = mask[b * YL + colBase + t];

    float acc[4][8][4];
#pragma unroll
    for (int i = 0; i < 4; ++i)
#pragma unroll
        for (int j = 0; j < 8; ++j)
#pragma unroll
            for (int d = 0; d < 4; ++d) acc[i][j][d] = 0.0f;

    const float* A  = xs + (size_t)b * XL * DD + (size_t)rowBase * DD;
    const float* Bp = ys + (size_t)b * YL * DD + (size_t)colBase * DD;

    for (int it = 0; it < 32; ++it) {
        const int k0 = it * 32;
#pragma unroll
        for (int i = 0; i < 8; ++i) {
            int s  = t + i * 128;
            int r  = s >> 3;
            int c4 = s & 7;
            unsigned off = (unsigned)r * 128u +
                           (((unsigned)c4 * 16u) ^ (((unsigned)(r & 7)) << 4));
            float4 va = *reinterpret_cast<const float4*>(A  + (size_t)r * DD + k0 + c4 * 4);
            float4 vb = *reinterpret_cast<const float4*>(Bp + (size_t)r * DD + k0 + c4 * 4);
            float4 h, l;
            split4(va, h, l);
            *reinterpret_cast<float4*>(smem + OFF_A_HI + off) = h;
            *reinterpret_cast<float4*>(smem + OFF_A_LO + off) = l;
            split4(vb, h, l);
            *reinterpret_cast<float4*>(smem + OFF_B_HI + off) = h;
            *reinterpret_cast<float4*>(smem + OFF_B_LO + off) = l;
        }
        __syncthreads();
        mma_chunk(sb, aRow, bRow, cA, cB, xr, acc);
        __syncthreads();
    }

    // Masked epilogue: d0,d1 -> (row, col..col+1), d2,d3 -> (row+8, ...)
    const int* ms = (const int*)(smem + OFF_MASK);
    float* wbase = w + (size_t)b * XL * YL + colBase;
    const int g = lane >> 2;
    const int cp = (lane & 3) * 2;
#pragma unroll
    for (int i = 0; i < 4; ++i) {
        const int row = rowBase + m0 + 16 * i + g;
#pragma unroll
        for (int j = 0; j < 8; ++j) {
            const int col = n0 + 8 * j + cp;
            const int mk0 = ms[col];
            const int mk1 = ms[col + 1];
            float2 v;
            v.x = mk0 ? acc[i][j][0] : NEG_INF;
            v.y = mk1 ? acc[i][j][1] : NEG_INF;
            *reinterpret_cast<float2*>(wbase + (size_t)row * YL + col) = v;
            v.x = mk0 ? acc[i][j][2] : NEG_INF;
            v.y = mk1 ? acc[i][j][3] : NEG_INF;
            *reinterpret_cast<float2*>(wbase + (size_t)(row + 8) * YL + col) = v;
        }
    }
}

// ---------------------------------------------------------------------------
// Kernel 2: in-place row softmax over YL=1024
// ---------------------------------------------------------------------------
__global__ __launch_bounds__(256)
void softmax_kernel(float* __restrict__ w)
{
    __shared__ float red[256];
    const int row = blockIdx.x;
    float* p = w + (size_t)row * YL;
    const int t = threadIdx.x;

    float4 v = reinterpret_cast<float4*>(p)[t];

    float m = fmaxf(fmaxf(v.x, v.y), fmaxf(v.z, v.w));
    red[t] = m;
    __syncthreads();
    for (int s = 128; s > 0; s >>= 1) {
        if (t < s) red[t] = fmaxf(red[t], red[t + s]);
        __syncthreads();
    }
    m = red[0];
    __syncthreads();

    float e0 = expf(v.x - m);
    float e1 = expf(v.y - m);
    float e2 = expf(v.z - m);
    float e3 = expf(v.w - m);

    red[t] = e0 + e1 + e2 + e3;
    __syncthreads();
    for (int s = 128; s > 0; s >>= 1) {
        if (t < s) red[t] += red[t + s];
        __syncthreads();
    }
    float inv = 1.0f / red[0];

    float4 o;
    o.x = e0 * inv; o.y = e1 * inv; o.z = e2 * inv; o.w = e3 * inv;
    reinterpret_cast<float4*>(p)[t] = o;
}

// ---------------------------------------------------------------------------
// Kernel 3: emb = weight @ ys (HMMA tf32 3x; ys transposed into K-major smem)
// ---------------------------------------------------------------------------
__global__ __launch_bounds__(128, 2)
void emb_tc_kernel(const float* __restrict__ w,
                   const float* __restrict__ ys,
                   float* __restrict__ emb)
{
    extern __shared__ char smem[];
    const unsigned sb = smem_u32(smem);
    const int t = threadIdx.x;
    const int wid = t >> 5;
    const int lane = t & 31;
    const int b = blockIdx.z;
    const int rowBase = blockIdx.y * 128;   // x
    const int colBase = blockIdx.x * 128;   // d

    const int m0 = (wid & 1) * 64;
    const int n0 = (wid >> 1) * 64;

    const unsigned xr = (unsigned)(lane & 7) << 4;
    const unsigned rA = (unsigned)((lane & 7) + ((lane >> 3) & 1) * 8);
    const unsigned cA = (unsigned)((lane >> 4) << 4);
    const unsigned rB = (unsigned)((lane & 7) + ((lane >> 4) & 1) * 8);
    const unsigned cB = (unsigned)(((lane >> 3) & 1) << 4);
    const unsigned aRow = ((unsigned)m0 + rA) * 128u;
    const unsigned bRow = ((unsigned)n0 + rB) * 128u;

    float acc[4][8][4];
#pragma unroll
    for (int i = 0; i < 4; ++i)
#pragma unroll
        for (int j = 0; j < 8; ++j)
#pragma unroll
            for (int d = 0; d < 4; ++d) acc[i][j][d] = 0.0f;

    const float* A   = w  + (size_t)b * XL * YL + (size_t)rowBase * YL;
    const float* Byb = ys + (size_t)b * YL * DD + colBase;

    const unsigned bnXor = ((unsigned)(t & 7)) << 4;  // row (t) swizzle xor

    for (int it = 0; it < 32; ++it) {
        const int k0 = it * 32;
        // A tile: K-contiguous rows of w
#pragma unroll
        for (int i = 0; i < 8; ++i) {
            int s  = t + i * 128;
            int r  = s >> 3;
            int c4 = s & 7;
            unsigned off = (unsigned)r * 128u +
                           (((unsigned)c4 * 16u) ^ (((unsigned)(r & 7)) << 4));
            float4 va = *reinterpret_cast<const float4*>(A + (size_t)r * YL + k0 + c4 * 4);
            float4 h, l;
            split4(va, h, l);
            *reinterpret_cast<float4*>(smem + OFF_A_HI + off) = h;
            *reinterpret_cast<float4*>(smem + OFF_A_LO + off) = l;
        }
        // B tile: ys rows k0..k0+31 x 128 d-cols -> smem [d][k] K-major.
        // thread t owns d-row t; gather 4 k-strided values -> STS.128.
        {
            const float* bp = Byb + (size_t)k0 * DD + t;
#pragma unroll
            for (int q = 0; q < 8; ++q) {
                float4 vv;
                vv.x = bp[(size_t)(q * 4 + 0) * DD];
                vv.y = bp[(size_t)(q * 4 + 1) * DD];
                vv.z = bp[(size_t)(q * 4 + 2) * DD];
                vv.w = bp[(size_t)(q * 4 + 3) * DD];
                float4 h, l;
                split4(vv, h, l);
                unsigned off = (unsigned)t * 128u + (((unsigned)q * 16u) ^ bnXor);
                *reinterpret_cast<float4*>(smem + OFF_B_HI + off) = h;
                *reinterpret_cast<float4*>(smem + OFF_B_LO + off) = l;
            }
        }
        __syncthreads();
        mma_chunk(sb, aRow, bRow, cA, cB, xr, acc);
        __syncthreads();
    }

    float* obase = emb + (size_t)b * XL * DD + colBase;
    const int g = lane >> 2;
    const int cp = (lane & 3) * 2;
#pragma unroll
    for (int i = 0; i < 4; ++i) {
        const int row = rowBase + m0 + 16 * i + g;
#pragma unroll
        for (int j = 0; j < 8; ++j) {
            const int col = n0 + 8 * j + cp;
            float2 v;
            v.x = acc[i][j][0];
            v.y = acc[i][j][1];
            *reinterpret_cast<float2*>(obase + (size_t)row * DD + col) = v;
            v.x = acc[i][j][2];
            v.y = acc[i][j][3];
            *reinterpret_cast<float2*>(obase + (size_t)(row + 8) * DD + col) = v;
        }
    }
}

// ---------------------------------------------------------------------------
extern "C" void kernel_launch(void* const* d_in, const int* in_sizes, int n_in,
                              void* d_out, int out_size)
{
    const float* xs   = (const float*)d_in[0];
    const float* ys   = (const float*)d_in[1];
    const int*   mask = (const int*)d_in[2];

    float* emb = (float*)d_out;                           // [B, XL, D]
    float* w   = (float*)d_out + (size_t)BB * XL * DD;    // [B, XL, YL]

    cudaFuncSetAttribute(scores_tc_kernel,
                         cudaFuncAttributeMaxDynamicSharedMemorySize, SMEM_BYTES);
    cudaFuncSetAttribute(emb_tc_kernel,
                         cudaFuncAttributeMaxDynamicSharedMemorySize, SMEM_BYTES);

    dim3 block(128);
    scores_tc_kernel<<<dim3(8, 8, BB), block, SMEM_BYTES>>>(xs, ys, mask, w);
    softmax_kernel<<<BB * XL, 256>>>(w);
    emb_tc_kernel<<<dim3(8, 8, BB), block, SMEM_BYTES>>>(w, ys, emb);
}